// round 1
// baseline (speedup 1.0000x reference)
#include <cuda_runtime.h>
#include <cuda_bf16.h>
#include <mma.h>
#include <math.h>

using namespace nvcuda;

// ---------------- problem dims (fixed by setup_inputs) ----------------
#define B_DIM 4096
#define I_DIM 512
#define H_DIM 1024
#define P_DIM 4
#define T_DIM 32
#define O_DIM 3
#define N_DIM (P_DIM * H_DIM)   // 4096
#define M_DIM (T_DIM * B_DIM)   // 131072
#define M_HALF (M_DIM / 2)      // 65536  (keep each scratch array < 2^31 bytes)

#define OUT_TOTAL (B_DIM*O_DIM + B_DIM*P_DIM + B_DIM*H_DIM)  // 4222976

// ---------------- device scratch (no allocations allowed) ----------------
__device__ __nv_bfloat16 g_Whi [I_DIM * N_DIM];   // lif_W split, [k=i][n=p*H+h]
__device__ __nv_bfloat16 g_Wmid[I_DIM * N_DIM];
__device__ __nv_bfloat16 g_Wlo [I_DIM * N_DIM];
__device__ float         g_encoded[B_DIM * I_DIM];
__device__ __nv_bfloat16 g_Aspk[(size_t)M_DIM * I_DIM];       // spikes as bf16, [m=t*B+b][i]
__device__ float         g_cur0[(size_t)M_HALF * N_DIM];      // current, first 16 t  (1 GB)
__device__ float         g_cur1[(size_t)M_HALF * N_DIM];      // current, last 16 t   (1 GB)
__device__ float         g_pw  [B_DIM * P_DIM];
__device__ float         g_msr [B_DIM * H_DIM];
__device__ float         g_hid [B_DIM * (H_DIM/2)];
__device__ float         g_outp[B_DIM * O_DIM];

// ---------------- prep: 3-way bf16 split of lif_W with layout transform ----------------
__global__ void prep_split_kernel(const float* __restrict__ lifW)
{
    int idx = blockIdx.x * blockDim.x + threadIdx.x;     // over P*I*H = 2^21
    if (idx >= P_DIM * I_DIM * H_DIM) return;
    int h = idx & (H_DIM - 1);
    int i = (idx >> 10) & (I_DIM - 1);
    int p = idx >> 19;
    float w = lifW[idx];
    __nv_bfloat16 hi = __float2bfloat16(w);
    float r1 = w - __bfloat162float(hi);
    __nv_bfloat16 mid = __float2bfloat16(r1);
    float r2 = r1 - __bfloat162float(mid);
    __nv_bfloat16 lo = __float2bfloat16(r2);
    int dst = i * N_DIM + p * H_DIM + h;
    g_Whi [dst] = hi;
    g_Wmid[dst] = mid;
    g_Wlo [dst] = lo;
}

// ---------------- fp32 SIMT GEMM (encoder + output head), 128x128x16 tiling ----------------
// EPI: 0 = none, 1 = sigmoid, 2 = relu
template<int EPI>
__global__ void __launch_bounds__(256) gemm_f32_kernel(
    const float* __restrict__ A, const float* __restrict__ Bmat,
    const float* __restrict__ bias, float* __restrict__ C,
    int M, int N, int K)
{
    __shared__ float As[16][132];   // transposed A tile [k][m]
    __shared__ float Bs[16][128];   // B tile [k][n]
    const int tid = threadIdx.x;
    const int bm = blockIdx.y, bn = blockIdx.x;
    const int tx = tid & 15, ty = tid >> 4;

    float acc[8][8];
    #pragma unroll
    for (int i = 0; i < 8; i++)
        #pragma unroll
        for (int j = 0; j < 8; j++) acc[i][j] = 0.0f;

    const int NK = K >> 4;
    for (int ks = 0; ks < NK; ks++) {
        int k0 = ks << 4;
        #pragma unroll
        for (int it = 0; it < 2; it++) {
            int c = tid + it * 256;          // 512 float4 chunks of A (128 rows x 4)
            int row = c >> 2, k4 = (c & 3) << 2;
            float4 v = *reinterpret_cast<const float4*>(
                A + (size_t)(bm * 128 + row) * K + k0 + k4);
            As[k4 + 0][row] = v.x; As[k4 + 1][row] = v.y;
            As[k4 + 2][row] = v.z; As[k4 + 3][row] = v.w;
        }
        #pragma unroll
        for (int it = 0; it < 2; it++) {
            int c = tid + it * 256;          // 512 float4 chunks of B (16 rows x 32)
            int row = c >> 5, n4 = (c & 31) << 2;
            *reinterpret_cast<float4*>(&Bs[row][n4]) =
                *reinterpret_cast<const float4*>(
                    Bmat + (size_t)(k0 + row) * N + bn * 128 + n4);
        }
        __syncthreads();
        #pragma unroll
        for (int k = 0; k < 16; k++) {
            float a[8], b[8];
            *reinterpret_cast<float4*>(&a[0]) = *reinterpret_cast<const float4*>(&As[k][ty * 8]);
            *reinterpret_cast<float4*>(&a[4]) = *reinterpret_cast<const float4*>(&As[k][ty * 8 + 4]);
            *reinterpret_cast<float4*>(&b[0]) = *reinterpret_cast<const float4*>(&Bs[k][tx * 8]);
            *reinterpret_cast<float4*>(&b[4]) = *reinterpret_cast<const float4*>(&Bs[k][tx * 8 + 4]);
            #pragma unroll
            for (int i = 0; i < 8; i++)
                #pragma unroll
                for (int j = 0; j < 8; j++)
                    acc[i][j] = fmaf(a[i], b[j], acc[i][j]);
        }
        __syncthreads();
    }

    #pragma unroll
    for (int i = 0; i < 8; i++) {
        int row = bm * 128 + ty * 8 + i;
        #pragma unroll
        for (int j = 0; j < 8; j++) {
            int col = bn * 128 + tx * 8 + j;
            float v = acc[i][j] + bias[col];
            if (EPI == 1) v = 1.0f / (1.0f + expf(-v));
            if (EPI == 2) v = fmaxf(v, 0.0f);
            C[(size_t)row * N + col] = v;
        }
    }
}

// ---------------- pathway selector: x @ sel_W + b -> softmax over P=4 ----------------
__global__ void sel_kernel(const float* __restrict__ x, const float* __restrict__ selW,
                           const float* __restrict__ selb)
{
    int warp = (blockIdx.x * blockDim.x + threadIdx.x) >> 5;
    int lane = threadIdx.x & 31;
    if (warp >= B_DIM) return;
    const float* xr = x + (size_t)warp * I_DIM;
    float s0 = 0, s1 = 0, s2 = 0, s3 = 0;
    for (int i = lane; i < I_DIM; i += 32) {
        float xv = xr[i];
        float4 w = reinterpret_cast<const float4*>(selW)[i];
        s0 = fmaf(xv, w.x, s0); s1 = fmaf(xv, w.y, s1);
        s2 = fmaf(xv, w.z, s2); s3 = fmaf(xv, w.w, s3);
    }
    #pragma unroll
    for (int off = 16; off > 0; off >>= 1) {
        s0 += __shfl_down_sync(0xffffffffu, s0, off);
        s1 += __shfl_down_sync(0xffffffffu, s1, off);
        s2 += __shfl_down_sync(0xffffffffu, s2, off);
        s3 += __shfl_down_sync(0xffffffffu, s3, off);
    }
    if (lane == 0) {
        s0 += selb[0]; s1 += selb[1]; s2 += selb[2]; s3 += selb[3];
        float mx = fmaxf(fmaxf(s0, s1), fmaxf(s2, s3));
        float e0 = expf(s0 - mx), e1 = expf(s1 - mx), e2 = expf(s2 - mx), e3 = expf(s3 - mx);
        float inv = 1.0f / (e0 + e1 + e2 + e3);
        g_pw[warp * 4 + 0] = e0 * inv;
        g_pw[warp * 4 + 1] = e1 * inv;
        g_pw[warp * 4 + 2] = e2 * inv;
        g_pw[warp * 4 + 3] = e3 * inv;
    }
}

// ---------------- expand spikes to bf16 A matrix [m=t*B+b][i] ----------------
__global__ void spike_kernel(const float* __restrict__ noise)
{
    int gid = blockIdx.x * blockDim.x + threadIdx.x;   // 16,777,216 threads, 4 elems each
    int i4 = gid & 127;            // i/4
    int bt = gid >> 7;             // b*32 + t
    int t = bt & 31;
    int b = bt >> 5;
    float4 nz = reinterpret_cast<const float4*>(noise)[(size_t)bt * 128 + i4];
    float4 ev = reinterpret_cast<const float4*>(g_encoded)[(size_t)b * 128 + i4];
    __nv_bfloat162 v01 = __floats2bfloat162_rn(nz.x < ev.x ? 1.0f : 0.0f,
                                               nz.y < ev.y ? 1.0f : 0.0f);
    __nv_bfloat162 v23 = __floats2bfloat162_rn(nz.z < ev.z ? 1.0f : 0.0f,
                                               nz.w < ev.w ? 1.0f : 0.0f);
    size_t m = (size_t)t * B_DIM + b;
    __nv_bfloat16* dst = g_Aspk + m * I_DIM + i4 * 4;
    *reinterpret_cast<__nv_bfloat162*>(dst)     = v01;
    *reinterpret_cast<__nv_bfloat162*>(dst + 2) = v23;
}

// ---------------- main GEMM: current = spikes @ (Whi + Wmid + Wlo), wmma bf16 ----------------
#define BM 128
#define BN 128
#define BK 32

struct GemmSmem {
    __nv_bfloat16 A [2][BM][BK + 8];         // 20480 B
    __nv_bfloat16 Bm[2][3][BK][BN + 8];      // 52224 B
};

__device__ __forceinline__ void cp16(void* dst, const void* src)
{
    unsigned d = (unsigned)__cvta_generic_to_shared(dst);
    asm volatile("cp.async.cg.shared.global [%0], [%1], 16;\n" :: "r"(d), "l"(src));
}

__global__ void __launch_bounds__(256) spike_gemm_kernel(
    const __nv_bfloat16* __restrict__ A, float* __restrict__ C)
{
    extern __shared__ char smem_raw[];
    GemmSmem& s = *reinterpret_cast<GemmSmem*>(smem_raw);
    const int tid = threadIdx.x;
    const int bn = blockIdx.x, bm = blockIdx.y;
    const int wid = tid >> 5;
    const int wm = wid >> 2, wn = wid & 3;    // 2 x 4 warp grid, warp tile 64x32

    wmma::fragment<wmma::accumulator, 16, 16, 16, float> acc[4][2];
    #pragma unroll
    for (int tm = 0; tm < 4; tm++)
        #pragma unroll
        for (int tn = 0; tn < 2; tn++)
            wmma::fill_fragment(acc[tm][tn], 0.0f);

    const __nv_bfloat16* Bp0 = g_Whi;
    const __nv_bfloat16* Bp1 = g_Wmid;
    const __nv_bfloat16* Bp2 = g_Wlo;

    auto load_stage = [&](int st, int ks) {
        int k0 = ks * BK;
        #pragma unroll
        for (int it = 0; it < 2; it++) {                    // A: 512 16B chunks
            int c = tid + it * 256;
            int row = c >> 2, cc = c & 3;
            cp16(&s.A[st][row][cc * 8],
                 A + (size_t)(bm * BM + row) * I_DIM + k0 + cc * 8);
        }
        #pragma unroll
        for (int it = 0; it < 2; it++) {                    // each B: 512 16B chunks
            int c = tid + it * 256;
            int row = c >> 4, cc = c & 15;
            size_t go = (size_t)(k0 + row) * N_DIM + bn * BN + cc * 8;
            cp16(&s.Bm[st][0][row][cc * 8], Bp0 + go);
            cp16(&s.Bm[st][1][row][cc * 8], Bp1 + go);
            cp16(&s.Bm[st][2][row][cc * 8], Bp2 + go);
        }
    };

    const int NK = I_DIM / BK;   // 16
    load_stage(0, 0);
    asm volatile("cp.async.commit_group;\n");
    for (int ks = 0; ks < NK; ks++) {
        if (ks + 1 < NK) load_stage((ks + 1) & 1, ks + 1);
        asm volatile("cp.async.commit_group;\n");
        asm volatile("cp.async.wait_group 1;\n");
        __syncthreads();
        int st = ks & 1;
        #pragma unroll
        for (int kk = 0; kk < BK; kk += 16) {
            wmma::fragment<wmma::matrix_b, 16, 16, 16, __nv_bfloat16, wmma::row_major> fb[3][2];
            #pragma unroll
            for (int tn = 0; tn < 2; tn++) {
                wmma::load_matrix_sync(fb[0][tn], &s.Bm[st][0][kk][wn * 32 + tn * 16], BN + 8);
                wmma::load_matrix_sync(fb[1][tn], &s.Bm[st][1][kk][wn * 32 + tn * 16], BN + 8);
                wmma::load_matrix_sync(fb[2][tn], &s.Bm[st][2][kk][wn * 32 + tn * 16], BN + 8);
            }
            #pragma unroll
            for (int tm = 0; tm < 4; tm++) {
                wmma::fragment<wmma::matrix_a, 16, 16, 16, __nv_bfloat16, wmma::row_major> fa;
                wmma::load_matrix_sync(fa, &s.A[st][wm * 64 + tm * 16][kk], BK + 8);
                #pragma unroll
                for (int tn = 0; tn < 2; tn++) {
                    wmma::mma_sync(acc[tm][tn], fa, fb[0][tn], acc[tm][tn]);
                    wmma::mma_sync(acc[tm][tn], fa, fb[1][tn], acc[tm][tn]);
                    wmma::mma_sync(acc[tm][tn], fa, fb[2][tn], acc[tm][tn]);
                }
            }
        }
        __syncthreads();
    }

    #pragma unroll
    for (int tm = 0; tm < 4; tm++)
        #pragma unroll
        for (int tn = 0; tn < 2; tn++) {
            float* cp = C + (size_t)(bm * BM + wm * 64 + tm * 16) * N_DIM
                          + bn * BN + wn * 32 + tn * 16;
            wmma::store_matrix_sync(cp, acc[tm][tn], N_DIM, wmma::mem_row_major);
        }
}

// ---------------- LIF recurrence over T, all P, one thread per (b,h) ----------------
__global__ void lif_kernel(const float* __restrict__ lifb)
{
    int idx = blockIdx.x * blockDim.x + threadIdx.x;   // over B*H
    int h = idx & (H_DIM - 1);
    int b = idx >> 10;
    float mem0 = 0, mem1 = 0, mem2 = 0, mem3 = 0;
    float ref0 = 0, ref1 = 0, ref2 = 0, ref3 = 0;
    float w0 = g_pw[b * 4 + 0], w1 = g_pw[b * 4 + 1];
    float w2 = g_pw[b * 4 + 2], w3 = g_pw[b * 4 + 3];
    float bb0 = lifb[0 * H_DIM + h], bb1 = lifb[1 * H_DIM + h];
    float bb2 = lifb[2 * H_DIM + h], bb3 = lifb[3 * H_DIM + h];
    float acc = 0.0f;

#define LIF_STEP(cur, MEM, REF, BB, W)                                        \
    {                                                                         \
        float c_ = (cur) + (BB);                                              \
        float m_ = fmaf(0.9f, MEM, c_);                                       \
        float sp_ = (m_ >= 1.0f && (REF) == 0.0f) ? 1.0f : 0.0f;              \
        MEM = m_ * (1.0f - sp_);                                              \
        REF = fmaxf((REF) - 1.0f + 2.0f * sp_, 0.0f);                         \
        acc = fmaf(sp_, W, acc);                                              \
    }

    #pragma unroll 4
    for (int t = 0; t < T_DIM / 2; t++) {
        size_t m = (size_t)t * B_DIM + b;
        const float* cur = g_cur0 + m * N_DIM + h;
        LIF_STEP(cur[0 * H_DIM], mem0, ref0, bb0, w0);
        LIF_STEP(cur[1 * H_DIM], mem1, ref1, bb1, w1);
        LIF_STEP(cur[2 * H_DIM], mem2, ref2, bb2, w2);
        LIF_STEP(cur[3 * H_DIM], mem3, ref3, bb3, w3);
    }
    #pragma unroll 4
    for (int t = 0; t < T_DIM / 2; t++) {
        size_t m = (size_t)t * B_DIM + b;
        const float* cur = g_cur1 + m * N_DIM + h;
        LIF_STEP(cur[0 * H_DIM], mem0, ref0, bb0, w0);
        LIF_STEP(cur[1 * H_DIM], mem1, ref1, bb1, w1);
        LIF_STEP(cur[2 * H_DIM], mem2, ref2, bb2, w2);
        LIF_STEP(cur[3 * H_DIM], mem3, ref3, bb3, w3);
    }
#undef LIF_STEP

    g_msr[idx] = acc * (1.0f / (float)T_DIM);
}

// ---------------- output head stage 2: out = hid @ W2 + b2 (N=3) ----------------
__global__ void out2_kernel(const float* __restrict__ W2, const float* __restrict__ b2)
{
    int warp = (blockIdx.x * blockDim.x + threadIdx.x) >> 5;
    int lane = threadIdx.x & 31;
    if (warp >= B_DIM) return;
    const float* hr = g_hid + (size_t)warp * (H_DIM / 2);
    float s0 = 0, s1 = 0, s2 = 0;
    for (int i = lane; i < H_DIM / 2; i += 32) {
        float v = hr[i];
        s0 = fmaf(v, W2[i * 3 + 0], s0);
        s1 = fmaf(v, W2[i * 3 + 1], s1);
        s2 = fmaf(v, W2[i * 3 + 2], s2);
    }
    #pragma unroll
    for (int off = 16; off > 0; off >>= 1) {
        s0 += __shfl_down_sync(0xffffffffu, s0, off);
        s1 += __shfl_down_sync(0xffffffffu, s1, off);
        s2 += __shfl_down_sync(0xffffffffu, s2, off);
    }
    if (lane == 0) {
        g_outp[warp * 3 + 0] = s0 + b2[0];
        g_outp[warp * 3 + 1] = s1 + b2[1];
        g_outp[warp * 3 + 2] = s2 + b2[2];
    }
}

// ---------------- assemble d_out = [output | pathway_weights | mean_spike_rate] ----------------
__global__ void assemble_kernel(float* __restrict__ dout, int out_size)
{
    int idx = blockIdx.x * blockDim.x + threadIdx.x;
    if (idx >= out_size) return;
    float v;
    if (out_size >= OUT_TOTAL) {
        if (idx < B_DIM * O_DIM)                    v = g_outp[idx];
        else if (idx < B_DIM * O_DIM + B_DIM * P_DIM) v = g_pw[idx - B_DIM * O_DIM];
        else                                        v = g_msr[idx - B_DIM * O_DIM - B_DIM * P_DIM];
    } else {
        v = (idx < B_DIM * O_DIM) ? g_outp[idx] : 0.0f;
    }
    dout[idx] = v;
}

// ---------------- launch ----------------
extern "C" void kernel_launch(void* const* d_in, const int* in_sizes, int n_in,
                              void* d_out, int out_size)
{
    const float* x     = (const float*)d_in[0];
    const float* noise = (const float*)d_in[1];
    int o = 2;
    if (n_in >= 13 && in_sizes[2] <= 4) o = 3;   // num_steps scalar present (unused: T fixed)
    const float* enc_W = (const float*)d_in[o + 0];
    const float* enc_b = (const float*)d_in[o + 1];
    const float* sel_W = (const float*)d_in[o + 2];
    const float* sel_b = (const float*)d_in[o + 3];
    const float* lif_W = (const float*)d_in[o + 4];
    const float* lif_b = (const float*)d_in[o + 5];
    const float* W1    = (const float*)d_in[o + 6];
    const float* b1    = (const float*)d_in[o + 7];
    const float* W2    = (const float*)d_in[o + 8];
    const float* b2    = (const float*)d_in[o + 9];
    float* dout = (float*)d_out;

    float* p_encoded; cudaGetSymbolAddress((void**)&p_encoded, g_encoded);
    float* p_msr;     cudaGetSymbolAddress((void**)&p_msr,     g_msr);
    float* p_hid;     cudaGetSymbolAddress((void**)&p_hid,     g_hid);
    float* p_cur0;    cudaGetSymbolAddress((void**)&p_cur0,    g_cur0);
    float* p_cur1;    cudaGetSymbolAddress((void**)&p_cur1,    g_cur1);
    __nv_bfloat16* p_Aspk; cudaGetSymbolAddress((void**)&p_Aspk, g_Aspk);

    // 1. split lif_W into 3x bf16 with [i][p*H+h] layout
    prep_split_kernel<<<(P_DIM * I_DIM * H_DIM + 255) / 256, 256>>>(lif_W);
    // 2. encoder: encoded = sigmoid(x @ enc_W + enc_b), pure fp32
    gemm_f32_kernel<1><<<dim3(I_DIM / 128, B_DIM / 128), 256>>>(
        x, enc_W, enc_b, p_encoded, B_DIM, I_DIM, I_DIM);
    // 3. pathway softmax
    sel_kernel<<<(B_DIM * 32 + 255) / 256, 256>>>(x, sel_W, sel_b);
    // 4. spike train -> bf16 A matrix
    spike_kernel<<<(M_DIM * (I_DIM / 4) + 255) / 256, 256>>>(noise);
    // 5. the big GEMM: current[t*B+b][p*H+h], split-bf16 3-term, two M-halves
    cudaFuncSetAttribute(spike_gemm_kernel,
                         cudaFuncAttributeMaxDynamicSharedMemorySize, (int)sizeof(GemmSmem));
    spike_gemm_kernel<<<dim3(N_DIM / BN, M_HALF / BM), 256, sizeof(GemmSmem)>>>(
        p_Aspk, p_cur0);
    spike_gemm_kernel<<<dim3(N_DIM / BN, M_HALF / BM), 256, sizeof(GemmSmem)>>>(
        p_Aspk + (size_t)M_HALF * I_DIM, p_cur1);
    // 6. LIF recurrence -> mean spike rate
    lif_kernel<<<(B_DIM * H_DIM) / 256, 256>>>(lif_b);
    // 7. head: hid = relu(msr @ W1 + b1), pure fp32
    gemm_f32_kernel<2><<<dim3((H_DIM / 2) / 128, B_DIM / 128), 256>>>(
        p_msr, W1, b1, p_hid, B_DIM, H_DIM / 2, H_DIM);
    // 8. head: out = hid @ W2 + b2
    out2_kernel<<<(B_DIM * 32 + 255) / 256, 256>>>(W2, b2);
    // 9. write d_out
    assemble_kernel<<<(out_size + 255) / 256, 256>>>(dout, out_size);
}

// round 6
// speedup vs baseline: 1.4421x; 1.4421x over previous
#include <cuda_runtime.h>
#include <cuda_bf16.h>
#include <cstdint>
#include <math.h>

// ---------------- problem dims (fixed by setup_inputs) ----------------
#define B_DIM 4096
#define I_DIM 512
#define H_DIM 1024
#define P_DIM 4
#define T_DIM 32
#define O_DIM 3
#define N_DIM (P_DIM * H_DIM)   // 4096
#define M_DIM (T_DIM * B_DIM)   // 131072   (m = b*T + t)

#define OUT_TOTAL (B_DIM*O_DIM + B_DIM*P_DIM + B_DIM*H_DIM)

// ---------------- device scratch ----------------
__device__ __nv_bfloat16 g_Whi [N_DIM * I_DIM];   // lif_W splits, [n=p*H+h][k=i] K-major
__device__ __nv_bfloat16 g_Wmid[N_DIM * I_DIM];
__device__ __nv_bfloat16 g_Wlo [N_DIM * I_DIM];
__device__ float         g_encoded[B_DIM * I_DIM];
__device__ __nv_bfloat16 g_Aspk[(size_t)M_DIM * I_DIM];   // spikes bf16, [m=b*T+t][i]
__device__ float         g_msrp[P_DIM][B_DIM * H_DIM];    // per-pathway LIF partials (64 MB)
__device__ float         g_pw  [B_DIM * P_DIM];
__device__ float         g_msr [B_DIM * H_DIM];
__device__ float         g_hid [B_DIM * (H_DIM/2)];
__device__ float         g_outp[B_DIM * O_DIM];

// ---------------- helpers ----------------
__device__ __forceinline__ uint32_t smem_u32(const void* p) {
    uint32_t a;
    asm("{ .reg .u64 t; cvta.to.shared.u64 t, %1; cvt.u32.u64 %0, t; }" : "=r"(a) : "l"(p));
    return a;
}
__device__ __forceinline__ void cp16(uint32_t dst_s, const void* src) {
    asm volatile("cp.async.cg.shared.global [%0], [%1], 16;\n" :: "r"(dst_s), "l"(src));
}
#define CP_COMMIT() asm volatile("cp.async.commit_group;\n" ::: "memory")

#define SW128(o) ((o) ^ (((o) >> 3) & 0x70))

__device__ __forceinline__ void ldsm4(uint32_t* r, uint32_t addr) {
    asm volatile("ldmatrix.sync.aligned.m8n8.x4.shared.b16 {%0,%1,%2,%3}, [%4];"
                 : "=r"(r[0]), "=r"(r[1]), "=r"(r[2]), "=r"(r[3]) : "r"(addr));
}
__device__ __forceinline__ void mma16816(float* c, const uint32_t* a,
                                         uint32_t b0, uint32_t b1) {
    asm volatile(
        "mma.sync.aligned.m16n8k16.row.col.f32.bf16.bf16.f32 "
        "{%0,%1,%2,%3}, {%4,%5,%6,%7}, {%8,%9}, {%0,%1,%2,%3};"
        : "+f"(c[0]), "+f"(c[1]), "+f"(c[2]), "+f"(c[3])
        : "r"(a[0]), "r"(a[1]), "r"(a[2]), "r"(a[3]), "r"(b0), "r"(b1));
}

// ---------------- prep: transpose lif_W to [n][k] + 3-way bf16 split ----------------
__global__ void prep_split_kernel(const float* __restrict__ lifW)
{
    __shared__ float tile[32][33];
    int p  = blockIdx.z;
    int i0 = blockIdx.y * 32;
    int h0 = blockIdx.x * 32;
    int tx = threadIdx.x & 31, ty = threadIdx.x >> 5;   // 32 x 8
    #pragma unroll
    for (int j = 0; j < 32; j += 8)
        tile[ty + j][tx] = lifW[((size_t)p * I_DIM + i0 + ty + j) * H_DIM + h0 + tx];
    __syncthreads();
    #pragma unroll
    for (int j = 0; j < 32; j += 8) {
        int h = h0 + ty + j, i = i0 + tx;
        float w = tile[tx][ty + j];
        __nv_bfloat16 hi = __float2bfloat16(w);
        float r1 = w - __bfloat162float(hi);
        __nv_bfloat16 mid = __float2bfloat16(r1);
        float r2 = r1 - __bfloat162float(mid);
        __nv_bfloat16 lo = __float2bfloat16(r2);
        size_t dst = (size_t)(p * H_DIM + h) * I_DIM + i;
        g_Whi [dst] = hi;
        g_Wmid[dst] = mid;
        g_Wlo [dst] = lo;
    }
}

// ---------------- fp32 SIMT GEMM (encoder + output head) ----------------
template<int EPI>
__global__ void __launch_bounds__(256) gemm_f32_kernel(
    const float* __restrict__ A, const float* __restrict__ Bmat,
    const float* __restrict__ bias, float* __restrict__ C,
    int M, int N, int K)
{
    __shared__ float As[16][132];
    __shared__ float Bs[16][128];
    const int tid = threadIdx.x;
    const int bm = blockIdx.y, bn = blockIdx.x;
    const int tx = tid & 15, ty = tid >> 4;

    float acc[8][8];
    #pragma unroll
    for (int i = 0; i < 8; i++)
        #pragma unroll
        for (int j = 0; j < 8; j++) acc[i][j] = 0.0f;

    const int NK = K >> 4;
    for (int ks = 0; ks < NK; ks++) {
        int k0 = ks << 4;
        #pragma unroll
        for (int it = 0; it < 2; it++) {
            int c = tid + it * 256;
            int row = c >> 2, k4 = (c & 3) << 2;
            float4 v = *reinterpret_cast<const float4*>(
                A + (size_t)(bm * 128 + row) * K + k0 + k4);
            As[k4 + 0][row] = v.x; As[k4 + 1][row] = v.y;
            As[k4 + 2][row] = v.z; As[k4 + 3][row] = v.w;
        }
        #pragma unroll
        for (int it = 0; it < 2; it++) {
            int c = tid + it * 256;
            int row = c >> 5, n4 = (c & 31) << 2;
            *reinterpret_cast<float4*>(&Bs[row][n4]) =
                *reinterpret_cast<const float4*>(
                    Bmat + (size_t)(k0 + row) * N + bn * 128 + n4);
        }
        __syncthreads();
        #pragma unroll
        for (int k = 0; k < 16; k++) {
            float a[8], b[8];
            *reinterpret_cast<float4*>(&a[0]) = *reinterpret_cast<const float4*>(&As[k][ty * 8]);
            *reinterpret_cast<float4*>(&a[4]) = *reinterpret_cast<const float4*>(&As[k][ty * 8 + 4]);
            *reinterpret_cast<float4*>(&b[0]) = *reinterpret_cast<const float4*>(&Bs[k][tx * 8]);
            *reinterpret_cast<float4*>(&b[4]) = *reinterpret_cast<const float4*>(&Bs[k][tx * 8 + 4]);
            #pragma unroll
            for (int i = 0; i < 8; i++)
                #pragma unroll
                for (int j = 0; j < 8; j++)
                    acc[i][j] = fmaf(a[i], b[j], acc[i][j]);
        }
        __syncthreads();
    }

    #pragma unroll
    for (int i = 0; i < 8; i++) {
        int row = bm * 128 + ty * 8 + i;
        #pragma unroll
        for (int j = 0; j < 8; j++) {
            int col = bn * 128 + tx * 8 + j;
            float v = acc[i][j] + bias[col];
            if (EPI == 1) v = 1.0f / (1.0f + expf(-v));
            if (EPI == 2) v = fmaxf(v, 0.0f);
            C[(size_t)row * N + col] = v;
        }
    }
}

// ---------------- pathway selector ----------------
__global__ void sel_kernel(const float* __restrict__ x, const float* __restrict__ selW,
                           const float* __restrict__ selb)
{
    int warp = (blockIdx.x * blockDim.x + threadIdx.x) >> 5;
    int lane = threadIdx.x & 31;
    if (warp >= B_DIM) return;
    const float* xr = x + (size_t)warp * I_DIM;
    float s0 = 0, s1 = 0, s2 = 0, s3 = 0;
    for (int i = lane; i < I_DIM; i += 32) {
        float xv = xr[i];
        float4 w = reinterpret_cast<const float4*>(selW)[i];
        s0 = fmaf(xv, w.x, s0); s1 = fmaf(xv, w.y, s1);
        s2 = fmaf(xv, w.z, s2); s3 = fmaf(xv, w.w, s3);
    }
    #pragma unroll
    for (int off = 16; off > 0; off >>= 1) {
        s0 += __shfl_down_sync(0xffffffffu, s0, off);
        s1 += __shfl_down_sync(0xffffffffu, s1, off);
        s2 += __shfl_down_sync(0xffffffffu, s2, off);
        s3 += __shfl_down_sync(0xffffffffu, s3, off);
    }
    if (lane == 0) {
        s0 += selb[0]; s1 += selb[1]; s2 += selb[2]; s3 += selb[3];
        float mx = fmaxf(fmaxf(s0, s1), fmaxf(s2, s3));
        float e0 = expf(s0 - mx), e1 = expf(s1 - mx), e2 = expf(s2 - mx), e3 = expf(s3 - mx);
        float inv = 1.0f / (e0 + e1 + e2 + e3);
        g_pw[warp * 4 + 0] = e0 * inv;
        g_pw[warp * 4 + 1] = e1 * inv;
        g_pw[warp * 4 + 2] = e2 * inv;
        g_pw[warp * 4 + 3] = e3 * inv;
    }
}

// ---------------- expand spikes to bf16 A matrix [m=b*T+t][i] ----------------
// m order == noise memory order [B][T][I]: pure streaming map.
__global__ void spike_kernel(const float* __restrict__ noise)
{
    int gid = blockIdx.x * blockDim.x + threadIdx.x;   // M*I/4 threads
    int i4 = gid & 127;            // i/4
    int m  = gid >> 7;             // b*T + t
    int b  = m >> 5;
    float4 nz = reinterpret_cast<const float4*>(noise)[(size_t)m * 128 + i4];
    float4 ev = reinterpret_cast<const float4*>(g_encoded)[(size_t)b * 128 + i4];
    __nv_bfloat162 v01 = __floats2bfloat162_rn(nz.x < ev.x ? 1.0f : 0.0f,
                                               nz.y < ev.y ? 1.0f : 0.0f);
    __nv_bfloat162 v23 = __floats2bfloat162_rn(nz.z < ev.z ? 1.0f : 0.0f,
                                               nz.w < ev.w ? 1.0f : 0.0f);
    __nv_bfloat16* dst = g_Aspk + (size_t)m * I_DIM + i4 * 4;
    *reinterpret_cast<__nv_bfloat162*>(dst)     = v01;
    *reinterpret_cast<__nv_bfloat162*>(dst + 2) = v23;
}

// ---------------- main GEMM + fused LIF ----------------
// C tile [128 m][128 n], m = b*32+t -> 4 batches x 32 timesteps per CTA.
// N tile of 128 cols lies within one pathway p = bn/8.
// After mainloop: stage C to SMEM, run 32-step LIF per (b,h), write msr_part[p][b][h].
#define STAGES 3
#define A_STAGE 16384            // 128 x 128B
#define B_STAGE 49152            // 3 matrices x 16384
#define SM_A 0
#define SM_B (STAGES * A_STAGE)  // 49152
#define SM_TOTAL (STAGES * (A_STAGE + B_STAGE))   // 196608 (also covers 128x132 f32 stage = 67584)
#define C_LD 132                 // f32 row stride for staged C tile

__global__ void __launch_bounds__(256, 1) spike_gemm_lif_kernel(
    const __nv_bfloat16* __restrict__ A, const float* __restrict__ lifb)
{
    extern __shared__ char smem[];
    const uint32_t sb = smem_u32(smem);
    const int tid = threadIdx.x;
    const int lane = tid & 31;
    const int wid = tid >> 5;
    const int wm = wid >> 2;       // 0..1
    const int wn = wid & 3;        // 0..3
    const int bn = blockIdx.x, bm = blockIdx.y;

    // ldmatrix per-lane address components (row&7 == lane&7 for both A and B)
    const uint32_t xr   = (uint32_t)(lane & 7) << 4;
    const uint32_t arow = (uint32_t)((lane & 7) + ((lane >> 3) & 1) * 8);
    const uint32_t acol = (uint32_t)((lane >> 4) << 4);       // 0 or 16
    const uint32_t brow = (uint32_t)((lane & 7) + ((lane >> 4) << 3));
    const uint32_t bcol = (uint32_t)(((lane >> 3) & 1) << 4);

    float acc[4][4][4];
    #pragma unroll
    for (int i = 0; i < 4; i++)
        #pragma unroll
        for (int j = 0; j < 4; j++)
            #pragma unroll
            for (int k = 0; k < 4; k++) acc[i][j][k] = 0.0f;

    const __nv_bfloat16* Abase = A + (size_t)bm * 128 * I_DIM;

    auto load_stage = [&](int st, int ks) {
        int k0 = ks * 64;
        const __nv_bfloat16* Ak = Abase + k0;
        #pragma unroll
        for (int it = 0; it < 4; it++) {
            int c = tid + it * 256;
            int r = c >> 3, cc = c & 7;
            cp16(sb + SM_A + st * A_STAGE + SW128(r * 128 + cc * 16),
                 Ak + (size_t)r * I_DIM + cc * 8);
        }
        const __nv_bfloat16* Wk0 = g_Whi  + (size_t)bn * 128 * I_DIM + k0;
        const __nv_bfloat16* Wk1 = g_Wmid + (size_t)bn * 128 * I_DIM + k0;
        const __nv_bfloat16* Wk2 = g_Wlo  + (size_t)bn * 128 * I_DIM + k0;
        #pragma unroll
        for (int it = 0; it < 4; it++) {
            int c = tid + it * 256;
            int r = c >> 3, cc = c & 7;
            uint32_t so = SW128(r * 128 + cc * 16);
            size_t go = (size_t)r * I_DIM + cc * 8;
            cp16(sb + SM_B + st * B_STAGE + 0 * 16384 + so, Wk0 + go);
            cp16(sb + SM_B + st * B_STAGE + 1 * 16384 + so, Wk1 + go);
            cp16(sb + SM_B + st * B_STAGE + 2 * 16384 + so, Wk2 + go);
        }
    };

    const int NKS = I_DIM / 64;   // 8
    load_stage(0, 0); CP_COMMIT();
    load_stage(1, 1); CP_COMMIT();

    for (int ks = 0; ks < NKS; ks++) {
        int st = ks % STAGES;
        if (ks < NKS - 1) asm volatile("cp.async.wait_group 1;\n" ::: "memory");
        else              asm volatile("cp.async.wait_group 0;\n" ::: "memory");
        __syncthreads();

        if (ks + 2 < NKS) { load_stage((ks + 2) % STAGES, ks + 2); CP_COMMIT(); }

        uint32_t aBase = sb + SM_A + st * A_STAGE + (wm * 64 + arow) * 128;
        uint32_t bBase = sb + SM_B + st * B_STAGE + (wn * 32 + brow) * 128;

        #pragma unroll
        for (int kk = 0; kk < 4; kk++) {
            uint32_t afrag[4][4];
            uint32_t aoff = (uint32_t)(kk * 32 + acol) ^ xr;
            #pragma unroll
            for (int mt = 0; mt < 4; mt++)
                ldsm4(afrag[mt], aBase + mt * 2048 + aoff);
            uint32_t boff = (uint32_t)(kk * 32 + bcol) ^ xr;
            #pragma unroll
            for (int j = 0; j < 3; j++) {
                uint32_t bfrag[2][4];
                #pragma unroll
                for (int nt = 0; nt < 2; nt++)
                    ldsm4(bfrag[nt], bBase + j * 16384 + nt * 2048 + boff);
                #pragma unroll
                for (int mt = 0; mt < 4; mt++) {
                    #pragma unroll
                    for (int nt = 0; nt < 2; nt++) {
                        mma16816(acc[mt][nt * 2 + 0], afrag[mt], bfrag[nt][0], bfrag[nt][1]);
                        mma16816(acc[mt][nt * 2 + 1], afrag[mt], bfrag[nt][2], bfrag[nt][3]);
                    }
                }
            }
        }
        __syncthreads();
    }

    // ---- stage C tile to SMEM (row stride C_LD floats) ----
    float* sC = reinterpret_cast<float*>(smem);
    {
        int r0 = wm * 64 + (lane >> 2);
        int c0 = wn * 32 + (lane & 3) * 2;
        #pragma unroll
        for (int mt = 0; mt < 4; mt++) {
            #pragma unroll
            for (int nt = 0; nt < 4; nt++) {
                float* p0 = sC + (size_t)(r0 + mt * 16) * C_LD + c0 + nt * 8;
                p0[0] = acc[mt][nt][0];
                p0[1] = acc[mt][nt][1];
                p0[8 * C_LD + 0] = acc[mt][nt][2];
                p0[8 * C_LD + 1] = acc[mt][nt][3];
            }
        }
    }
    __syncthreads();

    // ---- fused LIF over T=32 for each of 4 batches x 128 h ----
    // pair index q = b_local*128 + h_local; 512 pairs, 256 threads x 2.
    {
        const int p  = bn >> 3;                 // pathway (H_DIM/128 = 8 n-tiles per p)
        const int h0 = (bn & 7) * 128;          // h offset within pathway
        #pragma unroll
        for (int rep = 0; rep < 2; rep++) {
            int q = tid + rep * 256;
            int b_local = q >> 7;
            int h_local = q & 127;
            int b = bm * 4 + b_local;
            float bias = lifb[p * H_DIM + h0 + h_local];
            float w    = g_pw[b * 4 + p];
            const float* col = sC + (size_t)(b_local * 32) * C_LD + h_local;
            float mem = 0.0f, ref = 0.0f, accv = 0.0f;
            #pragma unroll
            for (int t = 0; t < T_DIM; t++) {
                float cur = col[t * C_LD] + bias;
                float m_ = fmaf(0.9f, mem, cur);
                float sp = (m_ >= 1.0f && ref == 0.0f) ? 1.0f : 0.0f;
                mem = m_ * (1.0f - sp);
                ref = fmaxf(ref - 1.0f + 2.0f * sp, 0.0f);
                accv = fmaf(sp, w, accv);
            }
            g_msrp[p][(size_t)b * H_DIM + h0 + h_local] = accv;
        }
    }
}

// ---------------- reduce pathway partials -> mean spike rate ----------------
__global__ void msr_reduce_kernel()
{
    int idx = blockIdx.x * blockDim.x + threadIdx.x;   // over B*H
    float s = g_msrp[0][idx] + g_msrp[1][idx] + g_msrp[2][idx] + g_msrp[3][idx];
    g_msr[idx] = s * (1.0f / (float)T_DIM);
}

// ---------------- output head stage 2 ----------------
__global__ void out2_kernel(const float* __restrict__ W2, const float* __restrict__ b2)
{
    int warp = (blockIdx.x * blockDim.x + threadIdx.x) >> 5;
    int lane = threadIdx.x & 31;
    if (warp >= B_DIM) return;
    const float* hr = g_hid + (size_t)warp * (H_DIM / 2);
    float s0 = 0, s1 = 0, s2 = 0;
    for (int i = lane; i < H_DIM / 2; i += 32) {
        float v = hr[i];
        s0 = fmaf(v, W2[i * 3 + 0], s0);
        s1 = fmaf(v, W2[i * 3 + 1], s1);
        s2 = fmaf(v, W2[i * 3 + 2], s2);
    }
    #pragma unroll
    for (int off = 16; off > 0; off >>= 1) {
        s0 += __shfl_down_sync(0xffffffffu, s0, off);
        s1 += __shfl_down_sync(0xffffffffu, s1, off);
        s2 += __shfl_down_sync(0xffffffffu, s2, off);
    }
    if (lane == 0) {
        g_outp[warp * 3 + 0] = s0 + b2[0];
        g_outp[warp * 3 + 1] = s1 + b2[1];
        g_outp[warp * 3 + 2] = s2 + b2[2];
    }
}

// ---------------- assemble d_out ----------------
__global__ void assemble_kernel(float* __restrict__ dout, int out_size)
{
    int idx = blockIdx.x * blockDim.x + threadIdx.x;
    if (idx >= out_size) return;
    float v;
    if (out_size >= OUT_TOTAL) {
        if (idx < B_DIM * O_DIM)                      v = g_outp[idx];
        else if (idx < B_DIM * O_DIM + B_DIM * P_DIM) v = g_pw[idx - B_DIM * O_DIM];
        else                                          v = g_msr[idx - B_DIM * O_DIM - B_DIM * P_DIM];
    } else {
        v = (idx < B_DIM * O_DIM) ? g_outp[idx] : 0.0f;
    }
    dout[idx] = v;
}

// ---------------- launch ----------------
extern "C" void kernel_launch(void* const* d_in, const int* in_sizes, int n_in,
                              void* d_out, int out_size)
{
    const float* x     = (const float*)d_in[0];
    const float* noise = (const float*)d_in[1];
    int o = 2;
    if (n_in >= 13 && in_sizes[2] <= 4) o = 3;
    const float* enc_W = (const float*)d_in[o + 0];
    const float* enc_b = (const float*)d_in[o + 1];
    const float* sel_W = (const float*)d_in[o + 2];
    const float* sel_b = (const float*)d_in[o + 3];
    const float* lif_W = (const float*)d_in[o + 4];
    const float* lif_b = (const float*)d_in[o + 5];
    const float* W1    = (const float*)d_in[o + 6];
    const float* b1    = (const float*)d_in[o + 7];
    const float* W2    = (const float*)d_in[o + 8];
    const float* b2    = (const float*)d_in[o + 9];
    float* dout = (float*)d_out;

    float* p_encoded; cudaGetSymbolAddress((void**)&p_encoded, g_encoded);
    float* p_msr;     cudaGetSymbolAddress((void**)&p_msr,     g_msr);
    float* p_hid;     cudaGetSymbolAddress((void**)&p_hid,     g_hid);
    __nv_bfloat16* p_Aspk; cudaGetSymbolAddress((void**)&p_Aspk, g_Aspk);

    // 1. transpose + 3-way split of lif_W -> [n][k] K-major bf16
    prep_split_kernel<<<dim3(H_DIM / 32, I_DIM / 32, P_DIM), 256>>>(lif_W);
    // 2. encoder
    gemm_f32_kernel<1><<<dim3(I_DIM / 128, B_DIM / 128), 256>>>(
        x, enc_W, enc_b, p_encoded, B_DIM, I_DIM, I_DIM);
    // 3. pathway softmax
    sel_kernel<<<(B_DIM * 32 + 255) / 256, 256>>>(x, sel_W, sel_b);
    // 4. spike train -> bf16 A (m = b*T+t, streaming)
    spike_kernel<<<(M_DIM * (I_DIM / 4) + 255) / 256, 256>>>(noise);
    // 5. main GEMM + fused LIF (single launch over full M)
    cudaFuncSetAttribute(spike_gemm_lif_kernel,
                         cudaFuncAttributeMaxDynamicSharedMemorySize, SM_TOTAL);
    spike_gemm_lif_kernel<<<dim3(N_DIM / 128, M_DIM / 128), 256, SM_TOTAL>>>(p_Aspk, lif_b);
    // 6. reduce pathway partials -> msr
    msr_reduce_kernel<<<(B_DIM * H_DIM) / 256, 256>>>();
    // 7. head
    gemm_f32_kernel<2><<<dim3((H_DIM / 2) / 128, B_DIM / 128), 256>>>(
        p_msr, W1, b1, p_hid, B_DIM, H_DIM / 2, H_DIM);
    out2_kernel<<<(B_DIM * 32 + 255) / 256, 256>>>(W2, b2);
    // 8. write d_out
    assemble_kernel<<<(out_size + 255) / 256, 256>>>(dout, out_size);
}